// round 2
// baseline (speedup 1.0000x reference)
#include <cuda_runtime.h>
#include <cstdint>

#define D 128
#define N_MAX 50064

// ---- device scratch (no allocations allowed) ----
__device__ float g_h[(size_t)N_MAX * D];   // h = x @ W
__device__ float g_deg[N_MAX];
__device__ float g_dis[N_MAX];
__device__ float g_colstats[2 * D];        // [0:128) sum, [128:256) sumsq

// ---------------------------------------------------------------------------
// K1: init deg = 1 (self loop), zero column stats
// ---------------------------------------------------------------------------
__global__ void k_init(int N) {
    int i = blockIdx.x * blockDim.x + threadIdx.x;
    if (i < N) g_deg[i] = 1.0f;
    if (blockIdx.x == 0 && threadIdx.x < 2 * D) g_colstats[threadIdx.x] = 0.0f;
}

// ---------------------------------------------------------------------------
// K2: deg[col] += 1 per positive edge  (edge indices are int32!)
// ---------------------------------------------------------------------------
__global__ void k_deg(const int* __restrict__ pos, int E) {
    int e = blockIdx.x * blockDim.x + threadIdx.x;
    if (e < E) {
        int col = pos[(size_t)E + e];
        atomicAdd(&g_deg[col], 1.0f);
    }
}

// ---------------------------------------------------------------------------
// K3: dis = rsqrt(deg)   (deg >= 1 always)
// ---------------------------------------------------------------------------
__global__ void k_dis(int N) {
    int i = blockIdx.x * blockDim.x + threadIdx.x;
    if (i < N) g_dis[i] = rsqrtf(g_deg[i]);
}

// ---------------------------------------------------------------------------
// K4: h = x @ W (register-tiled fp32 GEMM), fused epilogue:
//     g_h[r][c] = h;  out[r][c] = h * dis[r]^2   (self-loop init of accumulator)
// block = 256 threads, tile = 64 rows x 128 cols, thread = 8 rows x 4 cols
// ---------------------------------------------------------------------------
__global__ void k_gemm(const float* __restrict__ x, const float* __restrict__ W,
                       float* __restrict__ out, int N) {
    __shared__ float xs[16][64];    // transposed x tile: xs[k][row]
    __shared__ float ws[16][128];   // W tile

    const int t  = threadIdx.x;
    const int r0 = blockIdx.x * 64;
    const int cg = t & 31;          // column group: cols cg*4 .. cg*4+3
    const int rg = t >> 5;          // row group: rows rg*8 .. rg*8+7 (== warp id)

    float acc[8][4];
#pragma unroll
    for (int i = 0; i < 8; i++)
#pragma unroll
        for (int j = 0; j < 4; j++) acc[i][j] = 0.0f;

    for (int k0 = 0; k0 < D; k0 += 16) {
        __syncthreads();
        // load x tile (64 rows x 16 k) transposed into xs
        {
            int row = t >> 2;            // 0..63
            int kk  = (t & 3) * 4;       // 0,4,8,12
            float4 v = make_float4(0.f, 0.f, 0.f, 0.f);
            int gr = r0 + row;
            if (gr < N) v = *(const float4*)(x + (size_t)gr * D + k0 + kk);
            xs[kk + 0][row] = v.x;
            xs[kk + 1][row] = v.y;
            xs[kk + 2][row] = v.z;
            xs[kk + 3][row] = v.w;
        }
        // load W tile (16 k x 128 cols): 512 float4, 2 per thread
        {
#pragma unroll
            for (int u = 0; u < 2; u++) {
                int id = t + u * 256;    // 0..511
                int kk = id >> 5;
                int c4 = id & 31;
                float4 v = *(const float4*)(W + (size_t)(k0 + kk) * D + c4 * 4);
                *(float4*)&ws[kk][c4 * 4] = v;
            }
        }
        __syncthreads();

#pragma unroll
        for (int kk = 0; kk < 16; kk++) {
            float4 w  = *(float4*)&ws[kk][cg * 4];
            float4 xa = *(float4*)&xs[kk][rg * 8];
            float4 xb = *(float4*)&xs[kk][rg * 8 + 4];
            float xv[8] = {xa.x, xa.y, xa.z, xa.w, xb.x, xb.y, xb.z, xb.w};
#pragma unroll
            for (int i = 0; i < 8; i++) {
                acc[i][0] += xv[i] * w.x;
                acc[i][1] += xv[i] * w.y;
                acc[i][2] += xv[i] * w.z;
                acc[i][3] += xv[i] * w.w;
            }
        }
    }

#pragma unroll
    for (int i = 0; i < 8; i++) {
        int gr = r0 + rg * 8 + i;
        if (gr < N) {
            float s  = g_dis[gr];
            float sl = s * s;                       // self-loop norm = 1/deg
            float4 a = make_float4(acc[i][0], acc[i][1], acc[i][2], acc[i][3]);
            *(float4*)(g_h + (size_t)gr * D + cg * 4) = a;
            float4 o = make_float4(a.x * sl, a.y * sl, a.z * sl, a.w * sl);
            *(float4*)(out + (size_t)gr * D + cg * 4) = o;
        }
    }
}

// ---------------------------------------------------------------------------
// K5: edge scatter — one warp per edge:
//     out[col][:] += dis[row]*dis[col] * h[row][:]   via red.global.add.v4.f32
// ---------------------------------------------------------------------------
__global__ void k_scatter(const int* __restrict__ pos,
                          float* __restrict__ out, int E) {
    int gw   = (blockIdx.x * blockDim.x + threadIdx.x) >> 5;
    int lane = threadIdx.x & 31;
    if (gw >= E) return;

    int row = pos[gw];
    int col = pos[(size_t)E + gw];
    float nrm = g_dis[row] * g_dis[col];

    float4 v = *(const float4*)(g_h + (size_t)row * D + lane * 4);
    v.x *= nrm; v.y *= nrm; v.z *= nrm; v.w *= nrm;

    float* dst = out + (size_t)col * D + lane * 4;
    asm volatile("red.global.add.v4.f32 [%0], {%1, %2, %3, %4};"
                 :: "l"(dst), "f"(v.x), "f"(v.y), "f"(v.z), "f"(v.w)
                 : "memory");
}

// ---------------------------------------------------------------------------
// K6: per-column sum and sum-of-squares (axis-0 reduction)
// block = 128 threads, one thread per column; blocks stride over rows
// ---------------------------------------------------------------------------
__global__ void k_stats(const float* __restrict__ out, int N) {
    int c = threadIdx.x;
    float s = 0.0f, s2 = 0.0f;
    for (int r = blockIdx.x; r < N; r += gridDim.x) {
        float v = out[(size_t)r * D + c];
        s  += v;
        s2 += v * v;
    }
    atomicAdd(&g_colstats[c], s);
    atomicAdd(&g_colstats[D + c], s2);
}

// ---------------------------------------------------------------------------
// K7: BN (training-mode, biased var) + ReLU, in place on out
// ---------------------------------------------------------------------------
__global__ void k_final(const float* __restrict__ gamma,
                        const float* __restrict__ beta,
                        float* __restrict__ out, int N) {
    __shared__ float sscale[D], sshift[D];
    int t = threadIdx.x;
    if (t < D) {
        float invN = 1.0f / (float)N;
        float mean = g_colstats[t] * invN;
        float var  = g_colstats[D + t] * invN - mean * mean;
        float inv  = rsqrtf(var + 1e-5f);
        float sc   = gamma[t] * inv;
        sscale[t]  = sc;
        sshift[t]  = beta[t] - mean * sc;
    }
    __syncthreads();

    size_t total4 = (size_t)N * (D / 4);
    size_t stride = (size_t)gridDim.x * blockDim.x;
    for (size_t i = (size_t)blockIdx.x * blockDim.x + t; i < total4; i += stride) {
        int c = (int)(i & 31) * 4;
        float4 v = ((float4*)out)[i];
        v.x = fmaxf(v.x * sscale[c + 0] + sshift[c + 0], 0.0f);
        v.y = fmaxf(v.y * sscale[c + 1] + sshift[c + 1], 0.0f);
        v.z = fmaxf(v.z * sscale[c + 2] + sshift[c + 2], 0.0f);
        v.w = fmaxf(v.w * sscale[c + 3] + sshift[c + 3], 0.0f);
        ((float4*)out)[i] = v;
    }
}

// ---------------------------------------------------------------------------
extern "C" void kernel_launch(void* const* d_in, const int* in_sizes, int n_in,
                              void* d_out, int out_size) {
    const float* x     = (const float*)d_in[0];
    const int*   pos   = (const int*)d_in[1];   // int32 (JAX canonicalizes int64 -> int32)
    // d_in[2] = neg_edge_index: weight 0 => mathematically a no-op, skipped
    const float* W     = (const float*)d_in[3];
    // d_in[4] = b: cancels exactly inside BatchNorm, skipped
    const float* gamma = (const float*)d_in[5];
    const float* beta  = (const float*)d_in[6];
    float*       out   = (float*)d_out;

    const int N = in_sizes[0] / D;
    const int E = in_sizes[1] / 2;

    k_init<<<(N + 255) / 256, 256>>>(N);
    k_deg<<<(E + 255) / 256, 256>>>(pos, E);
    k_dis<<<(N + 255) / 256, 256>>>(N);
    k_gemm<<<(N + 63) / 64, 256>>>(x, W, out, N);
    // one warp per edge
    {
        long long threads = (long long)E * 32;
        int blocks = (int)((threads + 255) / 256);
        k_scatter<<<blocks, 256>>>(pos, out, E);
    }
    k_stats<<<512, 128>>>(out, N);
    k_final<<<1024, 256>>>(gamma, beta, out, N);
}

// round 3
// speedup vs baseline: 1.3733x; 1.3733x over previous
#include <cuda_runtime.h>
#include <cstdint>

#define D 128
#define N_MAX 50064
#define E_MAX 500000

// ---- device scratch (no allocations allowed) ----
__device__ float g_h[(size_t)N_MAX * D];   // h' = dis[row] * (x @ W)[row]
__device__ int   g_cnt[N_MAX];             // in-degree (excluding self-loop)
__device__ float g_dis[N_MAX];             // rsqrt(1 + cnt)
__device__ int   g_start[N_MAX];           // CSC segment start
__device__ int   g_cursor[N_MAX];          // fill cursor
__device__ int   g_adj[E_MAX];             // CSC: source rows grouped by col
__device__ int   g_part[256];              // block partial sums for scan
__device__ float g_colstats[2 * D];        // [0:128) sum, [128:256) sumsq

// ---------------------------------------------------------------------------
// K1: zero cnt + column stats
// ---------------------------------------------------------------------------
__global__ void k_init(int N) {
    int i = blockIdx.x * blockDim.x + threadIdx.x;
    if (i < N) g_cnt[i] = 0;
    if (blockIdx.x == 0 && threadIdx.x < 2 * D) g_colstats[threadIdx.x] = 0.0f;
}

// ---------------------------------------------------------------------------
// K2: in-degree count per positive edge (int32 indices)
// ---------------------------------------------------------------------------
__global__ void k_count(const int* __restrict__ pos, int E) {
    int e = blockIdx.x * blockDim.x + threadIdx.x;
    if (e < E) atomicAdd(&g_cnt[pos[(size_t)E + e]], 1);
}

// ---------------------------------------------------------------------------
// K3a: per-256-block partial sums of cnt
// ---------------------------------------------------------------------------
__global__ void k_scan1(int N) {
    __shared__ int sh[256];
    int i = blockIdx.x * 256 + threadIdx.x;
    sh[threadIdx.x] = (i < N) ? g_cnt[i] : 0;
    __syncthreads();
#pragma unroll
    for (int off = 128; off > 0; off >>= 1) {
        if (threadIdx.x < off) sh[threadIdx.x] += sh[threadIdx.x + off];
        __syncthreads();
    }
    if (threadIdx.x == 0) g_part[blockIdx.x] = sh[0];
}

// ---------------------------------------------------------------------------
// K3b: exclusive scan of the (<=256) block partials, single block
// ---------------------------------------------------------------------------
__global__ void k_scan2(int NB) {
    __shared__ int sh[256];
    int t = threadIdx.x;
    int v = (t < NB) ? g_part[t] : 0;
    sh[t] = v;
    __syncthreads();
    for (int off = 1; off < 256; off <<= 1) {
        int x = (t >= off) ? sh[t - off] : 0;
        __syncthreads();
        sh[t] += x;
        __syncthreads();
    }
    if (t < NB) g_part[t] = sh[t] - v;   // exclusive
}

// ---------------------------------------------------------------------------
// K3c: per-element starts (block-local scan + block offset); also dis, cursor
// ---------------------------------------------------------------------------
__global__ void k_scan3(int N) {
    __shared__ int sh[256];
    int t = threadIdx.x;
    int i = blockIdx.x * 256 + t;
    int v = (i < N) ? g_cnt[i] : 0;
    sh[t] = v;
    __syncthreads();
    for (int off = 1; off < 256; off <<= 1) {
        int x = (t >= off) ? sh[t - off] : 0;
        __syncthreads();
        sh[t] += x;
        __syncthreads();
    }
    if (i < N) {
        int start = g_part[blockIdx.x] + sh[t] - v;  // exclusive
        g_start[i]  = start;
        g_cursor[i] = start;
        g_dis[i]    = rsqrtf(1.0f + (float)v);
    }
}

// ---------------------------------------------------------------------------
// K4: fill CSC adjacency: g_adj[start[col]..] = rows of edges into col
// ---------------------------------------------------------------------------
__global__ void k_fill(const int* __restrict__ pos, int E) {
    int e = blockIdx.x * blockDim.x + threadIdx.x;
    if (e < E) {
        int col = pos[(size_t)E + e];
        int p = atomicAdd(&g_cursor[col], 1);
        g_adj[p] = pos[e];
    }
}

// ---------------------------------------------------------------------------
// K5: h' = dis[r] * (x @ W)  — fp32x2 packed-FMA GEMM
// block = 256 threads, tile = 128 rows x 128 cols, thread = 8 rows x 8 cols
// accumulators are packed f32x2 pairs over adjacent columns
// ---------------------------------------------------------------------------
#define FMA2(acc, a, b) asm("fma.rn.f32x2 %0, %1, %2, %0;" : "+l"(acc) : "l"(a), "l"(b))

__global__ void __launch_bounds__(256) k_gemm(const float* __restrict__ x,
                                              const float* __restrict__ W, int N) {
    __shared__ float xs[16][128];   // transposed x tile: xs[k][row]
    __shared__ float ws[16][128];   // W tile: ws[k][col]

    const int t  = threadIdx.x;
    const int r0 = blockIdx.x * 128;
    const int cg = t & 15;          // col group: cols cg*8 .. cg*8+7
    const int rg = t >> 4;          // row group: rows rg*8 .. rg*8+7

    unsigned long long acc[8][4];   // [row][colpair] packed (c, c+1)
#pragma unroll
    for (int i = 0; i < 8; i++)
#pragma unroll
        for (int j = 0; j < 4; j++) acc[i][j] = 0ull;

    for (int k0 = 0; k0 < D; k0 += 16) {
        __syncthreads();
        // x tile: 128 rows x 16 k, transposed into xs
#pragma unroll
        for (int u = 0; u < 2; u++) {
            int id  = t + u * 256;       // 0..511
            int row = id >> 2;           // 0..127
            int kq  = (id & 3) * 4;      // 0,4,8,12
            float4 v = make_float4(0.f, 0.f, 0.f, 0.f);
            int gr = r0 + row;
            if (gr < N) v = *(const float4*)(x + (size_t)gr * D + k0 + kq);
            xs[kq + 0][row] = v.x;
            xs[kq + 1][row] = v.y;
            xs[kq + 2][row] = v.z;
            xs[kq + 3][row] = v.w;
        }
        // W tile: 16 k x 128 cols
#pragma unroll
        for (int u = 0; u < 2; u++) {
            int id = t + u * 256;        // 0..511
            int kk = id >> 5;
            int c4 = id & 31;
            *(float4*)&ws[kk][c4 * 4] =
                *(const float4*)(W + (size_t)(k0 + kk) * D + c4 * 4);
        }
        __syncthreads();

#pragma unroll
        for (int kk = 0; kk < 16; kk++) {
            ulonglong2 wA = *(const ulonglong2*)&ws[kk][cg * 8];      // (c0,c1),(c2,c3)
            ulonglong2 wB = *(const ulonglong2*)&ws[kk][cg * 8 + 4];  // (c4,c5),(c6,c7)
            float4 xa = *(const float4*)&xs[kk][rg * 8];
            float4 xb = *(const float4*)&xs[kk][rg * 8 + 4];
            float xv[8] = {xa.x, xa.y, xa.z, xa.w, xb.x, xb.y, xb.z, xb.w};
#pragma unroll
            for (int i = 0; i < 8; i++) {
                unsigned long long xd;
                asm("mov.b64 %0, {%1, %1};" : "=l"(xd) : "f"(xv[i]));
                FMA2(acc[i][0], xd, wA.x);
                FMA2(acc[i][1], xd, wA.y);
                FMA2(acc[i][2], xd, wB.x);
                FMA2(acc[i][3], xd, wB.y);
            }
        }
    }

#pragma unroll
    for (int i = 0; i < 8; i++) {
        int gr = r0 + rg * 8 + i;
        if (gr < N) {
            float s = g_dis[gr];
            float c0 = __uint_as_float((unsigned)(acc[i][0] & 0xffffffffull));
            float c1 = __uint_as_float((unsigned)(acc[i][0] >> 32));
            float c2 = __uint_as_float((unsigned)(acc[i][1] & 0xffffffffull));
            float c3 = __uint_as_float((unsigned)(acc[i][1] >> 32));
            float c4 = __uint_as_float((unsigned)(acc[i][2] & 0xffffffffull));
            float c5 = __uint_as_float((unsigned)(acc[i][2] >> 32));
            float c6 = __uint_as_float((unsigned)(acc[i][3] & 0xffffffffull));
            float c7 = __uint_as_float((unsigned)(acc[i][3] >> 32));
            float4 o0 = make_float4(c0 * s, c1 * s, c2 * s, c3 * s);
            float4 o1 = make_float4(c4 * s, c5 * s, c6 * s, c7 * s);
            *(float4*)(g_h + (size_t)gr * D + cg * 8)     = o0;
            *(float4*)(g_h + (size_t)gr * D + cg * 8 + 4) = o1;
        }
    }
}

// ---------------------------------------------------------------------------
// K6: gather — one warp per node:
//     out[c] = dis[c] * ( h'[c] + sum_{edges into c} h'[row] )
// ---------------------------------------------------------------------------
__global__ void k_gather(float* __restrict__ out, int N) {
    int gw   = (blockIdx.x * blockDim.x + threadIdx.x) >> 5;
    int lane = threadIdx.x & 31;
    if (gw >= N) return;

    int start = g_start[gw];
    int cnt   = g_cnt[gw];

    float4 acc = *(const float4*)(g_h + (size_t)gw * D + lane * 4);  // self loop

    for (int j = 0; j < cnt; j += 32) {
        int m = min(32, cnt - j);
        int idx = (lane < m) ? g_adj[start + j + lane] : 0;
        int k = 0;
        for (; k + 4 <= m; k += 4) {     // 4-deep MLP
            int rA = __shfl_sync(0xffffffffu, idx, k + 0);
            int rB = __shfl_sync(0xffffffffu, idx, k + 1);
            int rC = __shfl_sync(0xffffffffu, idx, k + 2);
            int rD = __shfl_sync(0xffffffffu, idx, k + 3);
            float4 vA = *(const float4*)(g_h + (size_t)rA * D + lane * 4);
            float4 vB = *(const float4*)(g_h + (size_t)rB * D + lane * 4);
            float4 vC = *(const float4*)(g_h + (size_t)rC * D + lane * 4);
            float4 vD = *(const float4*)(g_h + (size_t)rD * D + lane * 4);
            acc.x += vA.x + vB.x + vC.x + vD.x;
            acc.y += vA.y + vB.y + vC.y + vD.y;
            acc.z += vA.z + vB.z + vC.z + vD.z;
            acc.w += vA.w + vB.w + vC.w + vD.w;
        }
        for (; k < m; k++) {
            int r = __shfl_sync(0xffffffffu, idx, k);
            float4 v = *(const float4*)(g_h + (size_t)r * D + lane * 4);
            acc.x += v.x; acc.y += v.y; acc.z += v.z; acc.w += v.w;
        }
    }

    float s = g_dis[gw];
    float4 o = make_float4(acc.x * s, acc.y * s, acc.z * s, acc.w * s);
    *(float4*)(out + (size_t)gw * D + lane * 4) = o;
}

// ---------------------------------------------------------------------------
// K7: per-column sum / sumsq (vectorized, block-level reduce, few atomics)
// ---------------------------------------------------------------------------
__global__ void k_stats(const float* __restrict__ out, int N) {
    __shared__ float ssum[8][128];
    __shared__ float ssq[8][128];
    int lane = threadIdx.x & 31;
    int w    = threadIdx.x >> 5;

    float4 s = make_float4(0.f, 0.f, 0.f, 0.f);
    float4 q = make_float4(0.f, 0.f, 0.f, 0.f);
    for (int r = blockIdx.x * 8 + w; r < N; r += gridDim.x * 8) {
        float4 v = *(const float4*)(out + (size_t)r * D + lane * 4);
        s.x += v.x; s.y += v.y; s.z += v.z; s.w += v.w;
        q.x += v.x * v.x; q.y += v.y * v.y; q.z += v.z * v.z; q.w += v.w * v.w;
    }
    *(float4*)&ssum[w][lane * 4] = s;
    *(float4*)&ssq[w][lane * 4]  = q;
    __syncthreads();

    int t = threadIdx.x;
    if (t < D) {
        float a = 0.f, b = 0.f;
#pragma unroll
        for (int w2 = 0; w2 < 8; w2++) { a += ssum[w2][t]; b += ssq[w2][t]; }
        atomicAdd(&g_colstats[t], a);
        atomicAdd(&g_colstats[D + t], b);
    }
}

// ---------------------------------------------------------------------------
// K8: BN (training mode, biased var) + ReLU, in place on out
// ---------------------------------------------------------------------------
__global__ void k_final(const float* __restrict__ gamma,
                        const float* __restrict__ beta,
                        float* __restrict__ out, int N) {
    __shared__ float sscale[D], sshift[D];
    int t = threadIdx.x;
    if (t < D) {
        float invN = 1.0f / (float)N;
        float mean = g_colstats[t] * invN;
        float var  = g_colstats[D + t] * invN - mean * mean;
        float inv  = rsqrtf(var + 1e-5f);
        float sc   = gamma[t] * inv;
        sscale[t]  = sc;
        sshift[t]  = beta[t] - mean * sc;
    }
    __syncthreads();

    size_t total4 = (size_t)N * (D / 4);
    size_t stride = (size_t)gridDim.x * blockDim.x;
    for (size_t i = (size_t)blockIdx.x * blockDim.x + t; i < total4; i += stride) {
        int c = (int)(i & 31) * 4;
        float4 v = ((float4*)out)[i];
        v.x = fmaxf(v.x * sscale[c + 0] + sshift[c + 0], 0.0f);
        v.y = fmaxf(v.y * sscale[c + 1] + sshift[c + 1], 0.0f);
        v.z = fmaxf(v.z * sscale[c + 2] + sshift[c + 2], 0.0f);
        v.w = fmaxf(v.w * sscale[c + 3] + sshift[c + 3], 0.0f);
        ((float4*)out)[i] = v;
    }
}

// ---------------------------------------------------------------------------
extern "C" void kernel_launch(void* const* d_in, const int* in_sizes, int n_in,
                              void* d_out, int out_size) {
    const float* x     = (const float*)d_in[0];
    const int*   pos   = (const int*)d_in[1];   // int32 (JAX canonicalizes int64)
    // d_in[2] = neg_edge_index: weight 0 => no-op, skipped
    const float* W     = (const float*)d_in[3];
    // d_in[4] = b: cancels exactly inside BatchNorm, skipped
    const float* gamma = (const float*)d_in[5];
    const float* beta  = (const float*)d_in[6];
    float*       out   = (float*)d_out;

    const int N  = in_sizes[0] / D;
    const int E  = in_sizes[1] / 2;
    const int NB = (N + 255) / 256;

    k_init <<<(N + 255) / 256, 256>>>(N);
    k_count<<<(E + 255) / 256, 256>>>(pos, E);
    k_scan1<<<NB, 256>>>(N);
    k_scan2<<<1, 256>>>(NB);
    k_scan3<<<NB, 256>>>(N);
    k_fill <<<(E + 255) / 256, 256>>>(pos, E);
    k_gemm <<<(N + 127) / 128, 256>>>(x, W, N);
    k_gather<<<(N * 32 + 255) / 256, 256>>>(out, N);
    k_stats<<<256, 256>>>(out, N);
    k_final<<<1024, 256>>>(gamma, beta, out, N);
}